// round 1
// baseline (speedup 1.0000x reference)
#include <cuda_runtime.h>
#include <cuda_bf16.h>
#include <cstdint>

#define NN 100000
#define DD 64
#define EE 800000

// Scratch (static device globals — allocation-free per harness rules)
__device__ float g_proj[4][(size_t)NN * DD];   // projected src features per relation
__device__ int   g_deg[4 * NN];                // per-relation in-degree of dst
__device__ float g_inv[4 * NN];                // 1 / max(deg, 1)

// ---------------------------------------------------------------------------
// Kernel 1: zero d_out (accumulators) and degree counters
// ---------------------------------------------------------------------------
__global__ __launch_bounds__(256) void zero_kernel(float4* __restrict__ out4) {
    int i = blockIdx.x * blockDim.x + threadIdx.x;
    const int OUT4 = 2 * NN * DD / 4;          // 3,200,000
    if (i < OUT4) out4[i] = make_float4(0.f, 0.f, 0.f, 0.f);
    if (i < 4 * NN) g_deg[i] = 0;
}

// ---------------------------------------------------------------------------
// Kernel 2: degree count (grid.y = relation)
// ---------------------------------------------------------------------------
struct Ptr4 { const int* p[4]; };

__global__ __launch_bounds__(256) void degree_kernel(Ptr4 dsts, int e_cnt) {
    const int* __restrict__ dst = dsts.p[blockIdx.y];
    int* deg = g_deg + blockIdx.y * NN;
    for (int i = blockIdx.x * blockDim.x + threadIdx.x; i < e_cnt;
         i += gridDim.x * blockDim.x)
        atomicAdd(&deg[dst[i]], 1);
}

// ---------------------------------------------------------------------------
// Kernel 3: inverse degree
// ---------------------------------------------------------------------------
__global__ __launch_bounds__(256) void invdeg_kernel() {
    int i = blockIdx.x * blockDim.x + threadIdx.x;
    if (i < 4 * NN) {
        int d = g_deg[i];
        g_inv[i] = 1.0f / (float)(d > 1 ? d : 1);
    }
}

// ---------------------------------------------------------------------------
// Kernel 4: projection Y[rel] = X @ W   (one warp per row, W in smem)
// ---------------------------------------------------------------------------
__global__ __launch_bounds__(256) void proj_kernel(const float* __restrict__ X,
                                                   const float* __restrict__ W,
                                                   int rel) {
    __shared__ float Ws[DD * DD];
    int t = threadIdx.x;
    {   // cooperative load of W (4096 floats, vectorized)
        const float4* W4 = (const float4*)W;
        float4* Ws4 = (float4*)Ws;
        for (int i = t; i < DD * DD / 4; i += 256) Ws4[i] = W4[i];
    }
    __syncthreads();

    float* __restrict__ Y = g_proj[rel];
    int lane = t & 31, warp = t >> 5;

    for (int row = blockIdx.x * 8 + warp; row < NN; row += gridDim.x * 8) {
        float xa = X[row * DD + lane];
        float xb = X[row * DD + 32 + lane];
        float acc0 = 0.f, acc1 = 0.f;
#pragma unroll
        for (int k = 0; k < 32; k++) {
            float xv = __shfl_sync(0xffffffffu, xa, k);
            acc0 = fmaf(xv, Ws[k * DD + lane], acc0);
            acc1 = fmaf(xv, Ws[k * DD + 32 + lane], acc1);
        }
#pragma unroll
        for (int k = 0; k < 32; k++) {
            float xv = __shfl_sync(0xffffffffu, xb, k);
            acc0 = fmaf(xv, Ws[(k + 32) * DD + lane], acc0);
            acc1 = fmaf(xv, Ws[(k + 32) * DD + 32 + lane], acc1);
        }
        Y[row * DD + lane]      = acc0;
        Y[row * DD + 32 + lane] = acc1;
    }
}

// ---------------------------------------------------------------------------
// Kernel 5: edge scatter — 16 lanes per edge, float4 gather + red.v4 scatter
// out[dst] += Y[src] * invdeg[dst]
// ---------------------------------------------------------------------------
__global__ __launch_bounds__(256) void scatter_kernel(int rel,
                                                      const int* __restrict__ src,
                                                      const int* __restrict__ dst,
                                                      float* __restrict__ out_base,
                                                      int e_cnt) {
    int gt = blockIdx.x * blockDim.x + threadIdx.x;
    int e = gt >> 4;
    if (e >= e_cnt) return;
    int l = gt & 15;

    int s = src[e];
    int d = dst[e];
    float sc = g_inv[rel * NN + d];

    const float4* __restrict__ Y4 = (const float4*)g_proj[rel];
    float4 v = Y4[(size_t)s * 16 + l];
    v.x *= sc; v.y *= sc; v.z *= sc; v.w *= sc;

    float* addr = out_base + (size_t)d * DD + l * 4;
    asm volatile("red.global.add.v4.f32 [%0], {%1, %2, %3, %4};"
                 :: "l"(addr), "f"(v.x), "f"(v.y), "f"(v.z), "f"(v.w)
                 : "memory");
}

// ---------------------------------------------------------------------------
// Kernel 6: bias + relu epilogue (vectorized)
// ---------------------------------------------------------------------------
__global__ __launch_bounds__(256) void bias_relu_kernel(float4* __restrict__ out4,
                                                        const float* __restrict__ bias) {
    int i = blockIdx.x * blockDim.x + threadIdx.x;
    const int OUT4 = 2 * NN * DD / 4;
    if (i >= OUT4) return;
    int j = (i * 4) & (DD - 1);
    float4 v = out4[i];
    v.x = fmaxf(v.x + bias[j + 0], 0.f);
    v.y = fmaxf(v.y + bias[j + 1], 0.f);
    v.z = fmaxf(v.z + bias[j + 2], 0.f);
    v.w = fmaxf(v.w + bias[j + 3], 0.f);
    out4[i] = v;
}

// ---------------------------------------------------------------------------
// Launch
// ---------------------------------------------------------------------------
extern "C" void kernel_launch(void* const* d_in, const int* in_sizes, int n_in,
                              void* d_out, int out_size) {
    const float* x_drug = (const float*)d_in[0];
    const float* x_gene = (const float*)d_in[1];
    const float* W_dd   = (const float*)d_in[2];
    const float* W_dg   = (const float*)d_in[3];
    const float* W_gd   = (const float*)d_in[4];
    const float* W_gg   = (const float*)d_in[5];
    const float* bias   = (const float*)d_in[6];
    const int* src_dd = (const int*)d_in[7];
    const int* dst_dd = (const int*)d_in[8];
    const int* src_dg = (const int*)d_in[9];
    const int* dst_dg = (const int*)d_in[10];
    const int* src_gd = (const int*)d_in[11];
    const int* dst_gd = (const int*)d_in[12];
    const int* src_gg = (const int*)d_in[13];
    const int* dst_gg = (const int*)d_in[14];
    float* out = (float*)d_out;           // [2, N, D]: out[0]=drug, out[1]=gene

    // 1) zero accumulators + degree counters
    {
        int total = 2 * NN * DD / 4;       // 3.2M float4 (covers 4*NN ints too)
        zero_kernel<<<(total + 255) / 256, 256>>>((float4*)out);
    }

    // 2) degrees: rel 0 = dd->drug, 1 = gd->drug, 2 = gg->gene, 3 = dg->gene
    {
        Ptr4 dsts;
        dsts.p[0] = dst_dd; dsts.p[1] = dst_gd; dsts.p[2] = dst_gg; dsts.p[3] = dst_dg;
        dim3 grid(2048, 4);
        degree_kernel<<<grid, 256>>>(dsts, EE);
    }

    // 3) inverse degrees
    invdeg_kernel<<<(4 * NN + 255) / 256, 256>>>();

    // 4) projections (rel index matches degree mapping)
    {
        int blocks = (NN + 7) / 8;
        proj_kernel<<<blocks, 256>>>(x_drug, W_dd, 0);
        proj_kernel<<<blocks, 256>>>(x_gene, W_gd, 1);
        proj_kernel<<<blocks, 256>>>(x_gene, W_gg, 2);
        proj_kernel<<<blocks, 256>>>(x_drug, W_dg, 3);
    }

    // 5) scatters (accumulate directly into d_out halves)
    {
        int blocks = ((EE * 16) + 255) / 256;   // 50000
        float* out_drug = out;
        float* out_gene = out + (size_t)NN * DD;
        scatter_kernel<<<blocks, 256>>>(0, src_dd, dst_dd, out_drug, EE);
        scatter_kernel<<<blocks, 256>>>(1, src_gd, dst_gd, out_drug, EE);
        scatter_kernel<<<blocks, 256>>>(2, src_gg, dst_gg, out_gene, EE);
        scatter_kernel<<<blocks, 256>>>(3, src_dg, dst_dg, out_gene, EE);
    }

    // 6) bias + relu
    {
        int total = 2 * NN * DD / 4;
        bias_relu_kernel<<<(total + 255) / 256, 256>>>((float4*)out, bias);
    }
}

// round 3
// speedup vs baseline: 1.1969x; 1.1969x over previous
#include <cuda_runtime.h>
#include <cuda_bf16.h>
#include <cstdint>

#define NN 100000
#define DD 64
#define EE 800000
#define BM 128

// Scratch (static device globals — allocation-free per harness rules)
// rel 0: dd (dst=drug), 1: gd (dst=drug), 2: gg (dst=gene), 3: dg (dst=gene)
__device__ float g_agg[4][(size_t)NN * DD];   // raw-feature aggregation per relation
__device__ int   g_deg[4 * NN];               // per-relation in-degree

__device__ __forceinline__ unsigned long long ffma2(unsigned long long a,
                                                    unsigned long long b,
                                                    unsigned long long c) {
    unsigned long long d;
    asm("fma.rn.f32x2 %0, %1, %2, %3;" : "=l"(d) : "l"(a), "l"(b), "l"(c));
    return d;
}

// ---------------------------------------------------------------------------
// Kernel 1: zero agg buffers + degree counters
// ---------------------------------------------------------------------------
__global__ __launch_bounds__(256) void zero_kernel() {
    int i = blockIdx.x * blockDim.x + threadIdx.x;
    const int AGG4 = 4 * NN * DD / 4;   // 6.4M float4
    float4* a4 = (float4*)&g_agg[0][0];
    if (i < AGG4) a4[i] = make_float4(0.f, 0.f, 0.f, 0.f);
    if (i < 4 * NN / 4) ((int4*)g_deg)[i] = make_int4(0, 0, 0, 0);
}

// ---------------------------------------------------------------------------
// Kernel 2: scatter raw features + degree count.
// 16 lanes per edge: agg[dst] += x[src] (red.v4), lane 0 bumps degree.
// ---------------------------------------------------------------------------
__global__ __launch_bounds__(256) void scatter_kernel(const float* __restrict__ X,
                                                      const int* __restrict__ src,
                                                      const int* __restrict__ dst,
                                                      int rel, int e_cnt) {
    int gt = blockIdx.x * blockDim.x + threadIdx.x;
    int e = gt >> 4;
    if (e >= e_cnt) return;
    int l = gt & 15;

    int s = src[e];
    int d = dst[e];

    const float4* __restrict__ X4 = (const float4*)X;
    float4 v = X4[(size_t)s * 16 + l];

    float* addr = &g_agg[rel][(size_t)d * DD + l * 4];
    asm volatile("red.global.add.v4.f32 [%0], {%1, %2, %3, %4};"
                 :: "l"(addr), "f"(v.x), "f"(v.y), "f"(v.z), "f"(v.w)
                 : "memory");
    if (l == 0) atomicAdd(&g_deg[rel * NN + d], 1);
}

// ---------------------------------------------------------------------------
// Kernel 3: fused projection
// out[type] = relu( (agg_r0/deg_r0) @ W_r0 + (agg_r1/deg_r1) @ W_r1 + bias )
// grid.y = dst type (0 = drug: rels 0,1 ; 1 = gene: rels 2,3)
// Register-tiled GEMM: block tile 128x64, thread tile 8x4, f32x2 FMA over k-pairs.
// ---------------------------------------------------------------------------
struct ProjArgs { const float* W[4]; const float* bias; float* out; };

__global__ __launch_bounds__(256, 2) void proj_fused_kernel(ProjArgs args) {
    __shared__ float Xs[BM][DD];     // 32 KB (row-major, scaled rows)
    __shared__ float Wt[DD][DD];     // 16 KB (transposed: Wt[n][k])

    int tid = threadIdx.x;
    int tc = tid & 15;               // col group: cols tc*4 .. tc*4+3
    int tr = tid >> 4;               // row group: rows tr*8 .. tr*8+7
    int row0 = blockIdx.x * BM;
    int grp = blockIdx.y;            // 0 = drug, 1 = gene

    // acc[i][c]: f32x2 pair (even-k partial, odd-k partial) for (row tr*8+i, col tc*4+c)
    unsigned long long acc[8][4];
#pragma unroll
    for (int i = 0; i < 8; i++)
#pragma unroll
        for (int c = 0; c < 4; c++) acc[i][c] = 0ull;

#pragma unroll
    for (int chunk = 0; chunk < 2; chunk++) {
        int rel = grp * 2 + chunk;
        const float* __restrict__ agg = g_agg[rel];
        const int* __restrict__ deg = g_deg + rel * NN;
        const float* __restrict__ W = args.W[rel];

        __syncthreads();   // protect previous chunk's smem reads

        // load X tile (scaled by 1/deg): 128 rows x 64 floats
#pragma unroll
        for (int j = 0; j < 8; j++) {
            int m = (tid >> 4) + j * 16;
            int r = row0 + m;
            float4 v = make_float4(0.f, 0.f, 0.f, 0.f);
            float sc = 0.f;
            if (r < NN) {
                v = ((const float4*)agg)[(size_t)r * 16 + tc];
                int dg = deg[r];
                sc = 1.0f / (float)(dg > 1 ? dg : 1);
            }
            v.x *= sc; v.y *= sc; v.z *= sc; v.w *= sc;
            *(float4*)&Xs[m][tc * 4] = v;
        }
        // load W transposed: Wt[n][k] = W[k][n]
#pragma unroll
        for (int j = 0; j < 4; j++) {
            int idx = tid + j * 256;       // float4 index over 1024
            int k = idx >> 4;
            int n4 = (idx & 15) * 4;
            float4 w = ((const float4*)W)[idx];
            Wt[n4 + 0][k] = w.x;
            Wt[n4 + 1][k] = w.y;
            Wt[n4 + 2][k] = w.z;
            Wt[n4 + 3][k] = w.w;
        }
        __syncthreads();

        const float* xrow = &Xs[tr * 8][0];
        const float* wcol = &Wt[tc * 4][0];
#pragma unroll 4
        for (int k = 0; k < DD; k += 2) {
            unsigned long long w2[4];
#pragma unroll
            for (int c = 0; c < 4; c++)
                w2[c] = *(const unsigned long long*)(wcol + c * DD + k);
#pragma unroll
            for (int i = 0; i < 8; i++) {
                unsigned long long x2 =
                    *(const unsigned long long*)(xrow + i * DD + k);
#pragma unroll
                for (int c = 0; c < 4; c++)
                    acc[i][c] = ffma2(x2, w2[c], acc[i][c]);
            }
        }
    }

    // epilogue: horizontal add of even/odd partials, bias, relu, store
    float4 bv = *(const float4*)&args.bias[tc * 4];
    float* out = args.out + (size_t)grp * NN * DD;
#pragma unroll
    for (int i = 0; i < 8; i++) {
        int r = row0 + tr * 8 + i;
        if (r >= NN) break;
        float2 p0 = *(float2*)&acc[i][0];
        float2 p1 = *(float2*)&acc[i][1];
        float2 p2 = *(float2*)&acc[i][2];
        float2 p3 = *(float2*)&acc[i][3];
        float4 o;
        o.x = fmaxf(p0.x + p0.y + bv.x, 0.f);
        o.y = fmaxf(p1.x + p1.y + bv.y, 0.f);
        o.z = fmaxf(p2.x + p2.y + bv.z, 0.f);
        o.w = fmaxf(p3.x + p3.y + bv.w, 0.f);
        ((float4*)out)[(size_t)r * 16 + tc] = o;
    }
}

// ---------------------------------------------------------------------------
// Launch
// ---------------------------------------------------------------------------
extern "C" void kernel_launch(void* const* d_in, const int* in_sizes, int n_in,
                              void* d_out, int out_size) {
    const float* x_drug = (const float*)d_in[0];
    const float* x_gene = (const float*)d_in[1];
    const float* W_dd   = (const float*)d_in[2];
    const float* W_dg   = (const float*)d_in[3];
    const float* W_gd   = (const float*)d_in[4];
    const float* W_gg   = (const float*)d_in[5];
    const float* bias   = (const float*)d_in[6];
    const int* src_dd = (const int*)d_in[7];
    const int* dst_dd = (const int*)d_in[8];
    const int* src_dg = (const int*)d_in[9];
    const int* dst_dg = (const int*)d_in[10];
    const int* src_gd = (const int*)d_in[11];
    const int* dst_gd = (const int*)d_in[12];
    const int* src_gg = (const int*)d_in[13];
    const int* dst_gg = (const int*)d_in[14];
    float* out = (float*)d_out;    // [2, N, D]: out[0]=drug, out[1]=gene

    // 1) zero agg + degree
    {
        int total = 4 * NN * DD / 4;    // 6.4M float4
        zero_kernel<<<(total + 255) / 256, 256>>>();
    }

    // 2) scatter raw features (+degree) per relation, sequential for L2 locality
    {
        int blocks = ((EE * 16) + 255) / 256;   // 50000
        scatter_kernel<<<blocks, 256>>>(x_drug, src_dd, dst_dd, 0, EE);
        scatter_kernel<<<blocks, 256>>>(x_gene, src_gd, dst_gd, 1, EE);
        scatter_kernel<<<blocks, 256>>>(x_gene, src_gg, dst_gg, 2, EE);
        scatter_kernel<<<blocks, 256>>>(x_drug, src_dg, dst_dg, 3, EE);
    }

    // 3) fused projection: scale + GEMM + sum(rel) + bias + relu
    {
        ProjArgs args;
        args.W[0] = W_dd; args.W[1] = W_gd; args.W[2] = W_gg; args.W[3] = W_dg;
        args.bias = bias; args.out = out;
        dim3 grid((NN + BM - 1) / BM, 2);
        proj_fused_kernel<<<grid, 256>>>(args);
    }
}